// round 14
// baseline (speedup 1.0000x reference)
#include <cuda_runtime.h>
#include <cuda_fp16.h>
#include <stdint.h>
#include <math.h>

// ---- fixed problem shape (HBlock_18597208391748) ----
#define BB   2
#define TT   4160
#define DD   1024
#define HH   16
#define KVH  4
#define HD   64
#define CS   2048
#define NU   (TT - CS)        // 2112
#define KVD  (KVH * HD)       // 256
#define DFF  (4 * DD)         // 4096
#define MQ   (BB * NU)        // 4224
#define MX   (BB * TT)        // 8320

// ---- scratch (device globals; no allocation allowed) ----
__device__ __half g_xnf[(size_t)MX * DD];
__device__ __half g_qbf[(size_t)MQ * DD];
__device__ __half g_kbf[(size_t)MX * KVD];
__device__ __half g_vbf[(size_t)MX * KVD];
__device__ __half g_af [(size_t)MQ * DD];
__device__ float  g_xnew[(size_t)MQ * DD];
__device__ __half g_x2f[(size_t)MQ * DD];
__device__ __half g_hf [(size_t)MQ * DFF];
__device__ __half g_wq[DD * DD];
__device__ __half g_wk[KVD * DD];
__device__ __half g_wv[KVD * DD];
__device__ __half g_wo[DD * DD];
__device__ __half g_wf[DFF * DD];
__device__ __half g_wp[DD * DFF];

// ============================================================
// PTX helpers
// ============================================================
__device__ __forceinline__ uint32_t smem_u32(const void* p) {
    uint32_t a;
    asm("{ .reg .u64 t; cvta.to.shared.u64 t, %1; cvt.u32.u64 %0, t; }" : "=r"(a) : "l"(p));
    return a;
}
#define CP_ASYNC16(dst, src) \
    asm volatile("cp.async.cg.shared.global [%0], [%1], 16;" :: "r"(dst), "l"(src))
#define CP_COMMIT() asm volatile("cp.async.commit_group;" ::: "memory")
#define CP_WAIT(n)  asm volatile("cp.async.wait_group %0;" :: "n"(n) : "memory")

__device__ __forceinline__ void ldsm4(uint32_t& r0, uint32_t& r1, uint32_t& r2, uint32_t& r3,
                                      uint32_t a) {
    asm volatile("ldmatrix.sync.aligned.m8n8.x4.shared.b16 {%0,%1,%2,%3}, [%4];"
                 : "=r"(r0), "=r"(r1), "=r"(r2), "=r"(r3) : "r"(a));
}
__device__ __forceinline__ void ldsm4t(uint32_t& r0, uint32_t& r1, uint32_t& r2, uint32_t& r3,
                                       uint32_t a) {
    asm volatile("ldmatrix.sync.aligned.m8n8.x4.trans.shared.b16 {%0,%1,%2,%3}, [%4];"
                 : "=r"(r0), "=r"(r1), "=r"(r2), "=r"(r3) : "r"(a));
}
__device__ __forceinline__ void mma_f16(float* d, const uint32_t* a, const uint32_t* b) {
    asm volatile("mma.sync.aligned.m16n8k16.row.col.f32.f16.f16.f32 "
                 "{%0,%1,%2,%3}, {%4,%5,%6,%7}, {%8,%9}, {%0,%1,%2,%3};"
                 : "+f"(d[0]), "+f"(d[1]), "+f"(d[2]), "+f"(d[3])
                 : "r"(a[0]), "r"(a[1]), "r"(a[2]), "r"(a[3]), "r"(b[0]), "r"(b[1]));
}
__device__ __forceinline__ void mma_f16h(uint32_t* d, const uint32_t* a, const uint32_t* b) {
    asm volatile("mma.sync.aligned.m16n8k16.row.col.f16.f16.f16.f16 "
                 "{%0,%1}, {%2,%3,%4,%5}, {%6,%7}, {%0,%1};"
                 : "+r"(d[0]), "+r"(d[1])
                 : "r"(a[0]), "r"(a[1]), "r"(a[2]), "r"(a[3]), "r"(b[0]), "r"(b[1]));
}
__device__ __forceinline__ uint32_t packh2(float lo, float hi) {
    __half2 h = __floats2half2_rn(lo, hi);
    return *reinterpret_cast<uint32_t*>(&h);
}
__device__ __forceinline__ __half2 u2h(uint32_t u) {
    return *reinterpret_cast<__half2*>(&u);
}
__device__ __forceinline__ uint32_t h2u(__half2 h) {
    return *reinterpret_cast<uint32_t*>(&h);
}
__device__ __forceinline__ float tanhfast(float x) {
    float e = __expf(2.0f * x);
    return (e - 1.0f) / (e + 1.0f);
}

// ============================================================
// fused prologue: weight cvts + rms_norm(x) + output prefix copy
// ============================================================
__global__ __launch_bounds__(256) void prep_k(
    const float* __restrict__ x,
    const float* __restrict__ Wq, const float* __restrict__ Wk,
    const float* __restrict__ Wv, const float* __restrict__ Wo,
    const float* __restrict__ Wfc, const float* __restrict__ Wproj,
    float* __restrict__ out, __half* __restrict__ xnf,
    __half* __restrict__ wq, __half* __restrict__ wk,
    __half* __restrict__ wv, __half* __restrict__ wo,
    __half* __restrict__ wf, __half* __restrict__ wp)
{
    const int bx = blockIdx.x;
    const int tid = threadIdx.x;
    __shared__ float red[8];

    if (bx < 5376) {
        const float* src; __half* dst; int base, n4;
        if (bx < 512)       { src = Wq;    dst = wq; base = 0;    n4 = 262144; }
        else if (bx < 640)  { src = Wk;    dst = wk; base = 512;  n4 = 65536; }
        else if (bx < 768)  { src = Wv;    dst = wv; base = 640;  n4 = 65536; }
        else if (bx < 1280) { src = Wo;    dst = wo; base = 768;  n4 = 262144; }
        else if (bx < 3328) { src = Wfc;   dst = wf; base = 1280; n4 = 1048576; }
        else                { src = Wproj; dst = wp; base = 3328; n4 = 1048576; }
        int i0 = ((bx - base) * 256 + tid) * 2;
        #pragma unroll
        for (int j = 0; j < 2; j++) {
            int i = i0 + j;
            if (i < n4) {
                float4 v = ((const float4*)src)[i];
                ((__half2*)dst)[2*i]     = __floats2half2_rn(v.x, v.y);
                ((__half2*)dst)[2*i + 1] = __floats2half2_rn(v.z, v.w);
            }
        }
    } else if (bx < 9472) {
        int i4 = (bx - 5376) * 256 + tid;
        int row = i4 >> 8, col = i4 & 255;
        int b = row >> 11, t = row & 2047;
        size_t g = ((size_t)(b * TT + t) << 8) + col;
        ((float4*)out)[g] = ((const float4*)x)[g];
    } else {
        const int row = bx - 9472;
        const float4* xr = (const float4*)x + (size_t)row * (DD / 4);
        float4 v = xr[tid];
        float ss = v.x * v.x + v.y * v.y + v.z * v.z + v.w * v.w;
        #pragma unroll
        for (int o = 16; o; o >>= 1) ss += __shfl_xor_sync(0xffffffffu, ss, o);
        if ((tid & 31) == 0) red[tid >> 5] = ss;
        __syncthreads();
        float tot = red[0] + red[1] + red[2] + red[3] + red[4] + red[5] + red[6] + red[7];
        float s = rsqrtf(tot * (1.0f / DD) + 1e-6f);
        size_t base = (size_t)row * (DD / 2) + 2 * tid;
        ((__half2*)xnf)[base]     = __floats2half2_rn(v.x * s, v.y * s);
        ((__half2*)xnf)[base + 1] = __floats2half2_rn(v.z * s, v.w * s);
    }
}

// ============================================================
// RMSNorm fp32 -> fp16 (x_new)
// ============================================================
__global__ __launch_bounds__(256) void rms_k(const float* __restrict__ x,
                                             __half* __restrict__ y)
{
    const int row = blockIdx.x;
    const float4* xr = (const float4*)x + (size_t)row * (DD / 4);
    float4 v = xr[threadIdx.x];
    float ss = v.x * v.x + v.y * v.y + v.z * v.z + v.w * v.w;
    #pragma unroll
    for (int o = 16; o; o >>= 1) ss += __shfl_xor_sync(0xffffffffu, ss, o);
    __shared__ float red[8];
    if ((threadIdx.x & 31) == 0) red[threadIdx.x >> 5] = ss;
    __syncthreads();
    float tot = red[0] + red[1] + red[2] + red[3] + red[4] + red[5] + red[6] + red[7];
    float s = rsqrtf(tot * (1.0f / DD) + 1e-6f);
    size_t base = (size_t)row * (DD / 2) + 2 * threadIdx.x;
    ((__half2*)y)[base]     = __floats2half2_rn(v.x * s, v.y * s);
    ((__half2*)y)[base + 1] = __floats2half2_rn(v.z * s, v.w * s);
}

// ============================================================
// fp16 HMMA GEMM, 3-stage cp.async pipeline, 1 sync/chunk.
// FACC: fp16 accumulators. kvsplit: merged K+V launch.
// epi: 1 softcap+R; 2 relu^2; 3 +R gathered; 4 l2norm head-major; 5 head-major
// ============================================================
template<bool FACC>
__global__ __launch_bounds__(256, 2)
void gemm_tc(const __half* __restrict__ Ah,
             const __half* __restrict__ Wh, const __half* __restrict__ Wl,
             float* __restrict__ C, __half* __restrict__ Ch,
             __half* __restrict__ HM, __half* __restrict__ HM2,
             const float* __restrict__ R,
             int Nglob, int K,
             int asl, int ast, int aso,
             int rsl, int rst, int rso,
             int SEQ, float sc, int epi, int kvsplit)
{
    extern __shared__ char smem[];
    const uint32_t sb = smem_u32(smem);
    const int tid = threadIdx.x;
    const int wid = tid >> 5;
    const int lane = tid & 31;
    const int bm = blockIdx.x * 128;
    const int nchunks = K >> 6;
    const uint32_t SS = 32768u;

    const __half* Wuse = Wh;
    __half* HMuse = HM;
    int epiu = epi;
    int bn = blockIdx.y * 128;
    if (kvsplit && (int)blockIdx.y >= kvsplit) {
        Wuse = Wl; HMuse = HM2; epiu = 5;
        bn = (blockIdx.y - kvsplit) * 128;
    }

    auto load_chunk = [&](int p, int c) {
        const int kc = c << 6;
        uint32_t bufb = sb + 1024 + p * SS;
        #pragma unroll
        for (int i = tid; i < 1024; i += 256) {
            int r = i >> 3, seg = i & 7;
            int row = bm + r;
            size_t ar = (size_t)(row / asl) * ast + aso + (row % asl);
            uint32_t off = (r << 7) + (seg << 4);
            uint32_t sw = off ^ ((off >> 3) & 0x70);
            CP_ASYNC16(bufb + sw, Ah + ar * K + kc + seg * 8);
        }
        #pragma unroll
        for (int i = tid; i < 1024; i += 256) {
            int r = i >> 3, seg = i & 7;
            uint32_t off = (r << 7) + (seg << 4);
            uint32_t sw = off ^ ((off >> 3) & 0x70);
            CP_ASYNC16(bufb + 16384 + sw, Wuse + (size_t)(bn + r) * K + kc + seg * 8);
        }
        CP_COMMIT();
    };

    const int warp_m = wid >> 1;
    const int warp_n = wid & 1;

    float acc[2][8][4];
    uint32_t acch[2][8][2];
    #pragma unroll
    for (int mf = 0; mf < 2; mf++)
        #pragma unroll
        for (int nf = 0; nf < 8; nf++) {
            if (FACC) { acch[mf][nf][0] = 0u; acch[mf][nf][1] = 0u; }
            else {
                #pragma unroll
                for (int j = 0; j < 4; j++) acc[mf][nf][j] = 0.f;
            }
        }

    load_chunk(0, 0);
    if (nchunks > 1) load_chunk(1, 1);

    const int a_row = warp_m * 32 + (lane & 15);
    const uint32_t a_koff = (lane >> 4) << 4;
    const int b_row = warp_n * 64 + ((lane >> 4) << 3) + (lane & 7);
    const uint32_t b_koff = ((lane >> 3) & 1) << 4;

    for (int c = 0; c < nchunks; c++) {
        if (c + 1 < nchunks) CP_WAIT(1);
        else CP_WAIT(0);
        __syncthreads();

        const uint32_t bA = sb + 1024 + (uint32_t)(c % 3) * SS;
        const uint32_t bW = bA + 16384;

        #pragma unroll
        for (int ks = 0; ks < 4; ks++) {
            const uint32_t kb = ks * 32;
            uint32_t ah[2][4];
            #pragma unroll
            for (int mf = 0; mf < 2; mf++) {
                uint32_t off = ((uint32_t)(a_row + mf * 16) << 7) + kb + a_koff;
                off ^= (off >> 3) & 0x70;
                ldsm4(ah[mf][0], ah[mf][1], ah[mf][2], ah[mf][3], bA + off);
            }
            #pragma unroll
            for (int nf2 = 0; nf2 < 4; nf2++) {
                uint32_t off = ((uint32_t)(b_row + nf2 * 16) << 7) + kb + b_koff;
                off ^= (off >> 3) & 0x70;
                uint32_t w0, w1, w2, w3;
                ldsm4(w0, w1, w2, w3, bW + off);
                uint32_t bb0[2] = {w0, w1}, bb1[2] = {w2, w3};
                if (FACC) {
                    mma_f16h(acch[0][2*nf2],   ah[0], bb0);
                    mma_f16h(acch[0][2*nf2+1], ah[0], bb1);
                    mma_f16h(acch[1][2*nf2],   ah[1], bb0);
                    mma_f16h(acch[1][2*nf2+1], ah[1], bb1);
                } else {
                    mma_f16(acc[0][2*nf2],   ah[0], bb0);
                    mma_f16(acc[0][2*nf2+1], ah[0], bb1);
                    mma_f16(acc[1][2*nf2],   ah[1], bb0);
                    mma_f16(acc[1][2*nf2+1], ah[1], bb1);
                }
            }
        }
        if (c + 2 < nchunks) load_chunk((c + 2) % 3, c + 2);
    }

    if (FACC) {
        #pragma unroll
        for (int mf = 0; mf < 2; mf++)
            #pragma unroll
            for (int nf = 0; nf < 8; nf++) {
                float2 lo = __half22float2(u2h(acch[mf][nf][0]));
                float2 hi = __half22float2(u2h(acch[mf][nf][1]));
                acc[mf][nf][0] = lo.x; acc[mf][nf][1] = lo.y;
                acc[mf][nf][2] = hi.x; acc[mf][nf][3] = hi.y;
            }
    }

    // ---- epilogue ----
    const int rq = lane >> 2, cq = (lane & 3) << 1;
    if (epiu >= 4) {
        const int headw = (bn + warp_n * 64) >> 6;
        const int heads = Nglob >> 6;
        #pragma unroll
        for (int mf = 0; mf < 2; mf++) {
            #pragma unroll
            for (int h2 = 0; h2 < 2; h2++) {
                const int rowg = bm + warp_m * 32 + mf * 16 + rq + h2 * 8;
                float s = 1.0f;
                if (epiu == 4) {
                    float ss = 0.f;
                    #pragma unroll
                    for (int nf = 0; nf < 8; nf++) {
                        float x0 = acc[mf][nf][2*h2], x1 = acc[mf][nf][2*h2+1];
                        ss += x0 * x0 + x1 * x1;
                    }
                    ss += __shfl_xor_sync(0xffffffffu, ss, 1);
                    ss += __shfl_xor_sync(0xffffffffu, ss, 2);
                    s = sc / fmaxf(sqrtf(ss), 1e-12f);
                }
                int b = rowg / SEQ, t = rowg - b * SEQ;
                __half* dst = HMuse + (((size_t)(b * heads + headw)) * SEQ + t) * 64;
                #pragma unroll
                for (int nf = 0; nf < 8; nf++) {
                    float x0 = acc[mf][nf][2*h2] * s, x1 = acc[mf][nf][2*h2+1] * s;
                    *(__half2*)(dst + nf * 8 + cq) = __floats2half2_rn(x0, x1);
                }
            }
        }
    } else {
        #pragma unroll
        for (int mf = 0; mf < 2; mf++) {
            #pragma unroll
            for (int h2 = 0; h2 < 2; h2++) {
                const int rowg = bm + warp_m * 32 + mf * 16 + rq + h2 * 8;
                #pragma unroll
                for (int nf = 0; nf < 8; nf++) {
                    float x0 = acc[mf][nf][2*h2], x1 = acc[mf][nf][2*h2+1];
                    const int colg = bn + warp_n * 64 + nf * 8 + cq;
                    if (epiu == 1) {
                        size_t rr = (size_t)(rowg / rsl) * rst + rso + (rowg % rsl);
                        const float* rp = R + rr * Nglob + colg;
                        float2 o;
                        o.x = rp[0] + 15.0f * tanhfast(x0 * (1.0f/15.0f));
                        o.y = rp[1] + 15.0f * tanhfast(x1 * (1.0f/15.0f));
                        *(float2*)(C + (size_t)rowg * Nglob + colg) = o;
                    } else if (epiu == 2) {
                        float a = fmaxf(x0, 0.f); a *= a;
                        float b = fmaxf(x1, 0.f); b *= b;
                        *(__half2*)(Ch + (size_t)rowg * Nglob + colg) = __floats2half2_rn(a, b);
                    } else {
                        const float* rp = R + (size_t)rowg * Nglob + colg;
                        size_t cr = (size_t)(rowg / rsl) * rst + rso + (rowg % rsl);
                        *(float2*)(C + cr * Nglob + colg) =
                            make_float2(rp[0] + x0, rp[1] + x1);
                    }
                }
            }
        }
    }
}

// ============================================================
// Flash attention, 4 heads/CTA (full GQA group shares one KV
// stream), 256 thr / 8 warps, 32 q-rows/warp (2 A-frags).
// S fp16-acc; P = cubic poly exp on half2; zero-mask after exp;
// PV f32-acc persistent (round-11 numerics, 2x warps for latency).
// smem: Q 4x8KB @0; 2 KV stages of 16KB @32768. Total 65536.
// ============================================================
__global__ __launch_bounds__(256, 2) void attn_mma(
    const __half* __restrict__ qbf,
    const __half* __restrict__ kbf,
    const __half* __restrict__ vbf,
    __half* __restrict__ o)
{
    extern __shared__ char sm[];
    const uint32_t sb = smem_u32(sm);
    const int tid = threadIdx.x;
    const int w = tid >> 5, l = tid & 31;
    const int wp = w >> 1;            // head within group (0..3)
    const int wh = w & 1;             // 32-row half of the 64-row tile
    const int qt = (int)gridDim.x - 1 - (int)blockIdx.x;   // longest first
    const int y = blockIdx.y;
    const int b = y >> 2, kvh = y & 3;
    const int head = kvh * 4 + wp;
    const int q0 = qt * 64;

    const __half* kg = kbf + ((size_t)(b * KVH + kvh) * TT) * 64;
    const __half* vg = vbf + ((size_t)(b * KVH + kvh) * TT) * 64;

    // Q load: four head tiles (32KB total)
    for (int i = tid; i < 2048; i += 256) {
        int hpi = i >> 9;
        int rem = i & 511;
        int r = rem >> 3, seg = rem & 7;
        const __half* src = qbf + (((size_t)(b * 16 + kvh * 4 + hpi)) * NU + q0 + r) * 64 + seg * 8;
        uint32_t off = (r << 7) + (seg << 4);
        uint32_t swo = off ^ ((off >> 3) & 0x70);
        CP_ASYNC16(sb + hpi * 8192 + swo, src);
    }
    const int n_kt = (CS >> 6) + qt + 1;
    auto load_kv = [&](int p, int c) {
        uint32_t base = sb + 32768 + p * 16384;
        const __half* ks = kg + (size_t)(c << 6) * 64;
        const __half* vs = vg + (size_t)(c << 6) * 64;
        for (int i = tid; i < 1024; i += 256) {
            int half = i >> 9;
            int rem = i & 511;
            int r = rem >> 3, seg = rem & 7;
            uint32_t off = (r << 7) + (seg << 4);
            uint32_t swo = off ^ ((off >> 3) & 0x70);
            const __half* src = (half ? vs : ks) + r * 64 + seg * 8;
            CP_ASYNC16(base + half * 8192 + swo, src);
        }
        CP_COMMIT();
    };
    load_kv(0, 0);

    float o_acc[2][8][4];
    #pragma unroll
    for (int mf = 0; mf < 2; mf++)
        #pragma unroll
        for (int j = 0; j < 8; j++)
            #pragma unroll
            for (int i = 0; i < 4; i++) o_acc[mf][j][i] = 0.f;
    float rsum[2][2] = {{0.f, 0.f}, {0.f, 0.f}};

    const int lrow = l & 15;
    const int lhi = l >> 4;
    const int cq = (l & 3) << 1;
    const int qpos0 = CS + q0 + wh * 32 + (l >> 2);
    const uint32_t qbase = sb + wp * 8192;

    const __half2 C6 = __float2half2_rn(0.16666667f);
    const __half2 C5 = __float2half2_rn(0.5f);
    const __half2 C1 = __float2half2_rn(1.0f);

    for (int c = 0; c < n_kt; c++) {
        const int p = c & 1;
        if (c + 1 < n_kt) { load_kv(1 - p, c + 1); CP_WAIT(1); }
        else              { CP_WAIT(0); }
        __syncthreads();
        const uint32_t kbase = sb + 32768 + p * 16384;
        const uint32_t vbase = kbase + 8192;

        // ---- S = Q K^T (fp16 accumulators, 2 A-frags per warp) ----
        uint32_t sh[2][8][2];
        #pragma unroll
        for (int mf = 0; mf < 2; mf++)
            #pragma unroll
            for (int j = 0; j < 8; j++) { sh[mf][j][0] = 0u; sh[mf][j][1] = 0u; }
        #pragma unroll
        for (int ks = 0; ks < 4; ks++) {
            uint32_t a[2][4];
            #pragma unroll
            for (int mf = 0; mf < 2; mf++) {
                uint32_t off = ((uint32_t)(wh * 32 + mf * 16 + lrow) << 7)
                             + ks * 32 + (lhi << 4);
                off ^= (off >> 3) & 0x70;
                ldsm4(a[mf][0], a[mf][1], a[mf][2], a[mf][3], qbase + off);
            }
            #pragma unroll
            for (int j = 0; j < 8; j += 2) {
                uint32_t off = ((uint32_t)((j + lhi) * 8 + (l & 7)) << 7)
                             + ks * 32 + (((l >> 3) & 1) << 4);
                off ^= (off >> 3) & 0x70;
                uint32_t b0, b1, b2, b3;
                ldsm4(b0, b1, b2, b3, kbase + off);
                uint32_t bb0[2] = {b0, b1}, bb1[2] = {b2, b3};
                mma_f16h(sh[0][j],     a[0], bb0);
                mma_f16h(sh[0][j + 1], a[0], bb1);
                mma_f16h(sh[1][j],     a[1], bb0);
                mma_f16h(sh[1][j + 1], a[1], bb1);
            }
        }

        // ---- P = exp(S) cubic poly on half2 ----
        #pragma unroll
        for (int mf = 0; mf < 2; mf++)
            #pragma unroll
            for (int j = 0; j < 8; j++) {
                #pragma unroll
                for (int r = 0; r < 2; r++) {
                    __half2 yv = u2h(sh[mf][j][r]);
                    __half2 t = __hfma2(yv, C6, C5);
                    t = __hfma2(yv, t, C1);
                    sh[mf][j][r] = h2u(__hfma2(yv, t, C1));
                }
            }

        // ---- causal zero-mask on diagonal tile ----
        if (c == n_kt - 1) {
            const int k0c = c * 64;
            #pragma unroll
            for (int mf = 0; mf < 2; mf++) {
                const int qp = qpos0 + mf * 16;
                #pragma unroll
                for (int j = 0; j < 8; j++) {
                    int col0 = k0c + j * 8 + cq;
                    float2 f0 = __half22float2(u2h(sh[mf][j][0]));
                    if (col0     > qp) f0.x = 0.f;
                    if (col0 + 1 > qp) f0.y = 0.f;
                    sh[mf][j][0] = packh2(f0.x, f0.y);
                    float2 f1 = __half22float2(u2h(sh[mf][j][1]));
                    if (col0     > qp + 8) f1.x = 0.f;
                    if (col0 + 1 > qp + 8) f1.y = 0.f;
                    sh[mf][j][1] = packh2(f1.x, f1.y);
                }
            }
        }

        // ---- row sums ----
        #pragma unroll
        for (int mf = 0; mf < 2; mf++) {
            __half2 t0 = u2h(sh[mf][0][0]), t1 = u2h(sh[mf][0][1]);
            #pragma unroll
            for (int j = 1; j < 8; j++) {
                t0 = __hadd2(t0, u2h(sh[mf][j][0]));
                t1 = __hadd2(t1, u2h(sh[mf][j][1]));
            }
            float2 f0 = __half22float2(t0);
            float2 f1 = __half22float2(t1);
            rsum[mf][0] += f0.x + f0.y;
            rsum[mf][1] += f1.x + f1.y;
        }

        // ---- O += P V (f32 acc; each V ldsm feeds both mf) ----
        #pragma unroll
        for (int ks = 0; ks < 4; ks++) {
            uint32_t a0[4] = {sh[0][2*ks][0], sh[0][2*ks][1], sh[0][2*ks+1][0], sh[0][2*ks+1][1]};
            uint32_t a1[4] = {sh[1][2*ks][0], sh[1][2*ks][1], sh[1][2*ks+1][0], sh[1][2*ks+1][1]};
            #pragma unroll
            for (int j = 0; j < 8; j += 2) {
                uint32_t off = ((uint32_t)(ks * 16 + lrow) << 7) + ((j + lhi) << 4);
                off ^= (off >> 3) & 0x70;
                uint32_t b0, b1, b2, b3;
                ldsm4t(b0, b1, b2, b3, vbase + off);
                uint32_t bb0[2] = {b0, b1}, bb1[2] = {b2, b3};
                mma_f16(o_acc[0][j],     a0, bb0);
                mma_f16(o_acc[0][j + 1], a0, bb1);
                mma_f16(o_acc[1][j],     a1, bb0);
                mma_f16(o_acc[1][j + 1], a1, bb1);
            }
        }
        __syncthreads();
    }

    #pragma unroll
    for (int mf = 0; mf < 2; mf++) {
        float r0 = rsum[mf][0], r1 = rsum[mf][1];
        r0 += __shfl_xor_sync(0xffffffffu, r0, 1);
        r0 += __shfl_xor_sync(0xffffffffu, r0, 2);
        r1 += __shfl_xor_sync(0xffffffffu, r1, 1);
        r1 += __shfl_xor_sync(0xffffffffu, r1, 2);
        const float inv0 = 1.0f / r0, inv1 = 1.0f / r1;

        const size_t gr0 = (size_t)(b * NU + q0 + wh * 32 + mf * 16 + (l >> 2));
        const size_t gr1 = gr0 + 8;
        const int colb = head * 64 + cq;
        #pragma unroll
        for (int j = 0; j < 8; j++) {
            const int col = colb + j * 8;
            *(__half2*)(o + gr0 * DD + col) =
                __floats2half2_rn(o_acc[mf][j][0] * inv0, o_acc[mf][j][1] * inv0);
            *(__half2*)(o + gr1 * DD + col) =
                __floats2half2_rn(o_acc[mf][j][2] * inv1, o_acc[mf][j][3] * inv1);
        }
    }
}

// ============================================================
extern "C" void kernel_launch(void* const* d_in, const int* in_sizes, int n_in,
                              void* d_out, int out_size)
{
    const float* x     = (const float*)d_in[0];
    const float* Wq    = (const float*)d_in[1];
    const float* Wk    = (const float*)d_in[2];
    const float* Wv    = (const float*)d_in[3];
    const float* Wo    = (const float*)d_in[4];
    const float* Wfc   = (const float*)d_in[5];
    const float* Wproj = (const float*)d_in[6];
    float* out = (float*)d_out;

    __half *xnf, *qbf, *kbf, *vbf, *af, *x2f, *hf;
    __half *wq, *wk, *wv, *wo, *wf, *wp;
    float *xnew;
    cudaGetSymbolAddress((void**)&xnf, g_xnf);
    cudaGetSymbolAddress((void**)&qbf, g_qbf);
    cudaGetSymbolAddress((void**)&kbf, g_kbf);
    cudaGetSymbolAddress((void**)&vbf, g_vbf);
    cudaGetSymbolAddress((void**)&af,  g_af);
    cudaGetSymbolAddress((void**)&xnew, g_xnew);
    cudaGetSymbolAddress((void**)&x2f, g_x2f);
    cudaGetSymbolAddress((void**)&hf,  g_hf);
    cudaGetSymbolAddress((void**)&wq,  g_wq);
    cudaGetSymbolAddress((void**)&wk,  g_wk);
    cudaGetSymbolAddress((void**)&wv,  g_wv);
    cudaGetSymbolAddress((void**)&wo,  g_wo);
    cudaGetSymbolAddress((void**)&wf,  g_wf);
    cudaGetSymbolAddress((void**)&wp,  g_wp);

    const int SMG = 1024 + 3 * 32768;   // 99328
    const int SMA = 65536;              // Q 4x8K + 2x16K
    cudaFuncSetAttribute(gemm_tc<true>,  cudaFuncAttributeMaxDynamicSharedMemorySize, SMG);
    cudaFuncSetAttribute(gemm_tc<false>, cudaFuncAttributeMaxDynamicSharedMemorySize, SMG);
    cudaFuncSetAttribute(attn_mma, cudaFuncAttributeMaxDynamicSharedMemorySize, SMA);

    // 1. fused prologue
    prep_k<<<17792, 256>>>(x, Wq, Wk, Wv, Wo, Wfc, Wproj,
                           out, xnf, wq, wk, wv, wo, wf, wp);

    // 2. K+V projection (merged), fp16 acc
    gemm_tc<true><<<dim3(MX / 128, 4), 256, SMG>>>(xnf, wk, wv,
        nullptr, nullptr, kbf, vbf, nullptr,
        KVD, DD, MX, MX, 0, 0, 0, 0, TT, 1.0f, 4, 2);
    // 3. Q projection (l2norm * 0.125), fp16 acc
    gemm_tc<true><<<dim3(MQ / 128, DD / 128), 256, SMG>>>(xnf, wq, nullptr,
        nullptr, nullptr, qbf, nullptr, nullptr,
        DD, DD, NU, TT, CS, 0, 0, 0, NU, 0.125f, 4, 0);

    // 4. flash attention (4 heads/CTA, 32 rows/warp)
    attn_mma<<<dim3(NU / 64, BB * KVH), 256, SMA>>>(qbf, kbf, vbf, af);

    // 5. x_new = x_upd + softcap(attn @ Wo^T), fp16 acc
    gemm_tc<true><<<dim3(MQ / 128, DD / 128), 256, SMG>>>(af, wo, nullptr,
        xnew, nullptr, nullptr, nullptr, x,
        DD, DD, MQ, MQ, 0, NU, TT, CS, 0, 0.f, 1, 0);

    // 6. FFN (f32 acc)
    rms_k<<<MQ, 256>>>(xnew, x2f);
    gemm_tc<false><<<dim3(MQ / 128, DFF / 128), 256, SMG>>>(x2f, wf, nullptr,
        nullptr, hf, nullptr, nullptr, nullptr,
        DFF, DD, MQ, MQ, 0, 0, 0, 0, 0, 0.f, 2, 0);
    gemm_tc<false><<<dim3(MQ / 128, DD / 128), 256, SMG>>>(hf, wp, nullptr,
        out, nullptr, nullptr, nullptr, xnew,
        DD, DFF, MQ, MQ, 0, NU, TT, CS, 0, 0.f, 3, 0);
}

// round 15
// speedup vs baseline: 1.1356x; 1.1356x over previous
#include <cuda_runtime.h>
#include <cuda_fp16.h>
#include <stdint.h>
#include <math.h>

// ---- fixed problem shape (HBlock_18597208391748) ----
#define BB   2
#define TT   4160
#define DD   1024
#define HH   16
#define KVH  4
#define HD   64
#define CS   2048
#define NU   (TT - CS)        // 2112
#define KVD  (KVH * HD)       // 256
#define DFF  (4 * DD)         // 4096
#define MQ   (BB * NU)        // 4224
#define MX   (BB * TT)        // 8320

// ---- scratch (device globals; no allocation allowed) ----
__device__ __half g_xnf[(size_t)MX * DD];
__device__ __half g_qbf[(size_t)MQ * DD];
__device__ __half g_kbf[(size_t)MX * KVD];
__device__ __half g_vbf[(size_t)MX * KVD];
__device__ __half g_af [(size_t)MQ * DD];
__device__ float  g_xnew[(size_t)MQ * DD];
__device__ __half g_x2f[(size_t)MQ * DD];
__device__ __half g_hf [(size_t)MQ * DFF];
__device__ __half g_wq[DD * DD];
__device__ __half g_wk[KVD * DD];
__device__ __half g_wv[KVD * DD];
__device__ __half g_wo[DD * DD];
__device__ __half g_wf[DFF * DD];
__device__ __half g_wp[DD * DFF];

// ============================================================
// PTX helpers
// ============================================================
__device__ __forceinline__ uint32_t smem_u32(const void* p) {
    uint32_t a;
    asm("{ .reg .u64 t; cvta.to.shared.u64 t, %1; cvt.u32.u64 %0, t; }" : "=r"(a) : "l"(p));
    return a;
}
#define CP_ASYNC16(dst, src) \
    asm volatile("cp.async.cg.shared.global [%0], [%1], 16;" :: "r"(dst), "l"(src))
#define CP_COMMIT() asm volatile("cp.async.commit_group;" ::: "memory")
#define CP_WAIT(n)  asm volatile("cp.async.wait_group %0;" :: "n"(n) : "memory")

__device__ __forceinline__ void ldsm4(uint32_t& r0, uint32_t& r1, uint32_t& r2, uint32_t& r3,
                                      uint32_t a) {
    asm volatile("ldmatrix.sync.aligned.m8n8.x4.shared.b16 {%0,%1,%2,%3}, [%4];"
                 : "=r"(r0), "=r"(r1), "=r"(r2), "=r"(r3) : "r"(a));
}
__device__ __forceinline__ void ldsm4t(uint32_t& r0, uint32_t& r1, uint32_t& r2, uint32_t& r3,
                                       uint32_t a) {
    asm volatile("ldmatrix.sync.aligned.m8n8.x4.trans.shared.b16 {%0,%1,%2,%3}, [%4];"
                 : "=r"(r0), "=r"(r1), "=r"(r2), "=r"(r3) : "r"(a));
}
__device__ __forceinline__ void mma_f16(float* d, const uint32_t* a, const uint32_t* b) {
    asm volatile("mma.sync.aligned.m16n8k16.row.col.f32.f16.f16.f32 "
                 "{%0,%1,%2,%3}, {%4,%5,%6,%7}, {%8,%9}, {%0,%1,%2,%3};"
                 : "+f"(d[0]), "+f"(d[1]), "+f"(d[2]), "+f"(d[3])
                 : "r"(a[0]), "r"(a[1]), "r"(a[2]), "r"(a[3]), "r"(b[0]), "r"(b[1]));
}
__device__ __forceinline__ void mma_f16h(uint32_t* d, const uint32_t* a, const uint32_t* b) {
    asm volatile("mma.sync.aligned.m16n8k16.row.col.f16.f16.f16.f16 "
                 "{%0,%1}, {%2,%3,%4,%5}, {%6,%7}, {%0,%1};"
                 : "+r"(d[0]), "+r"(d[1])
                 : "r"(a[0]), "r"(a[1]), "r"(a[2]), "r"(a[3]), "r"(b[0]), "r"(b[1]));
}
__device__ __forceinline__ uint32_t packh2(float lo, float hi) {
    __half2 h = __floats2half2_rn(lo, hi);
    return *reinterpret_cast<uint32_t*>(&h);
}
__device__ __forceinline__ __half2 u2h(uint32_t u) {
    return *reinterpret_cast<__half2*>(&u);
}
__device__ __forceinline__ uint32_t h2u(__half2 h) {
    return *reinterpret_cast<uint32_t*>(&h);
}
__device__ __forceinline__ float tanhfast(float x) {
    float e = __expf(2.0f * x);
    return (e - 1.0f) / (e + 1.0f);
}

// ============================================================
// fused prologue: weight cvts + rms_norm(x) + output prefix copy
// ============================================================
__global__ __launch_bounds__(256) void prep_k(
    const float* __restrict__ x,
    const float* __restrict__ Wq, const float* __restrict__ Wk,
    const float* __restrict__ Wv, const float* __restrict__ Wo,
    const float* __restrict__ Wfc, const float* __restrict__ Wproj,
    float* __restrict__ out, __half* __restrict__ xnf,
    __half* __restrict__ wq, __half* __restrict__ wk,
    __half* __restrict__ wv, __half* __restrict__ wo,
    __half* __restrict__ wf, __half* __restrict__ wp)
{
    const int bx = blockIdx.x;
    const int tid = threadIdx.x;
    __shared__ float red[8];

    if (bx < 5376) {
        const float* src; __half* dst; int base, n4;
        if (bx < 512)       { src = Wq;    dst = wq; base = 0;    n4 = 262144; }
        else if (bx < 640)  { src = Wk;    dst = wk; base = 512;  n4 = 65536; }
        else if (bx < 768)  { src = Wv;    dst = wv; base = 640;  n4 = 65536; }
        else if (bx < 1280) { src = Wo;    dst = wo; base = 768;  n4 = 262144; }
        else if (bx < 3328) { src = Wfc;   dst = wf; base = 1280; n4 = 1048576; }
        else                { src = Wproj; dst = wp; base = 3328; n4 = 1048576; }
        int i0 = ((bx - base) * 256 + tid) * 2;
        #pragma unroll
        for (int j = 0; j < 2; j++) {
            int i = i0 + j;
            if (i < n4) {
                float4 v = ((const float4*)src)[i];
                ((__half2*)dst)[2*i]     = __floats2half2_rn(v.x, v.y);
                ((__half2*)dst)[2*i + 1] = __floats2half2_rn(v.z, v.w);
            }
        }
    } else if (bx < 9472) {
        int i4 = (bx - 5376) * 256 + tid;
        int row = i4 >> 8, col = i4 & 255;
        int b = row >> 11, t = row & 2047;
        size_t g = ((size_t)(b * TT + t) << 8) + col;
        ((float4*)out)[g] = ((const float4*)x)[g];
    } else {
        const int row = bx - 9472;
        const float4* xr = (const float4*)x + (size_t)row * (DD / 4);
        float4 v = xr[tid];
        float ss = v.x * v.x + v.y * v.y + v.z * v.z + v.w * v.w;
        #pragma unroll
        for (int o = 16; o; o >>= 1) ss += __shfl_xor_sync(0xffffffffu, ss, o);
        if ((tid & 31) == 0) red[tid >> 5] = ss;
        __syncthreads();
        float tot = red[0] + red[1] + red[2] + red[3] + red[4] + red[5] + red[6] + red[7];
        float s = rsqrtf(tot * (1.0f / DD) + 1e-6f);
        size_t base = (size_t)row * (DD / 2) + 2 * tid;
        ((__half2*)xnf)[base]     = __floats2half2_rn(v.x * s, v.y * s);
        ((__half2*)xnf)[base + 1] = __floats2half2_rn(v.z * s, v.w * s);
    }
}

// ============================================================
// RMSNorm fp32 -> fp16 (x_new)
// ============================================================
__global__ __launch_bounds__(256) void rms_k(const float* __restrict__ x,
                                             __half* __restrict__ y)
{
    const int row = blockIdx.x;
    const float4* xr = (const float4*)x + (size_t)row * (DD / 4);
    float4 v = xr[threadIdx.x];
    float ss = v.x * v.x + v.y * v.y + v.z * v.z + v.w * v.w;
    #pragma unroll
    for (int o = 16; o; o >>= 1) ss += __shfl_xor_sync(0xffffffffu, ss, o);
    __shared__ float red[8];
    if ((threadIdx.x & 31) == 0) red[threadIdx.x >> 5] = ss;
    __syncthreads();
    float tot = red[0] + red[1] + red[2] + red[3] + red[4] + red[5] + red[6] + red[7];
    float s = rsqrtf(tot * (1.0f / DD) + 1e-6f);
    size_t base = (size_t)row * (DD / 2) + 2 * threadIdx.x;
    ((__half2*)y)[base]     = __floats2half2_rn(v.x * s, v.y * s);
    ((__half2*)y)[base + 1] = __floats2half2_rn(v.z * s, v.w * s);
}

// ============================================================
// fp16 HMMA GEMM, 3-stage cp.async pipeline, 1 sync/chunk.
// FACC: fp16 accumulators. kvsplit modes:
//   0: plain single GEMM
//   2: merged QKV launch — y<2: K (Wh->HM, l2norm); y<4: V (Wl->HM2);
//      y>=4: Q (Wq->HMq, l2norm*0.125, gathered rows, x<33 only)
// epi: 1 softcap+R; 2 relu^2; 3 +R gathered; 4 l2norm head-major; 5 head-major
// ============================================================
template<bool FACC>
__global__ __launch_bounds__(256, 2)
void gemm_tc(const __half* __restrict__ Ah,
             const __half* __restrict__ Wh, const __half* __restrict__ Wl,
             float* __restrict__ C, __half* __restrict__ Ch,
             __half* __restrict__ HM, __half* __restrict__ HM2,
             const float* __restrict__ R,
             const __half* __restrict__ Wq2, __half* __restrict__ HMq,
             int Nglob, int K,
             int asl, int ast, int aso,
             int rsl, int rst, int rso,
             int SEQ, float sc, int epi, int kvsplit)
{
    extern __shared__ char smem[];
    const uint32_t sb = smem_u32(smem);
    const int tid = threadIdx.x;
    const int wid = tid >> 5;
    const int lane = tid & 31;
    const int bm = blockIdx.x * 128;
    const int nchunks = K >> 6;
    const uint32_t SS = 32768u;

    const __half* Wuse = Wh;
    __half* HMuse = HM;
    int epiu = epi;
    int bn = blockIdx.y * 128;
    int Nloc = Nglob, asll = asl, astl = ast, asol = aso, SEQl = SEQ;
    float scl = sc;
    if (kvsplit == 2) {
        const int y = blockIdx.y;
        if (y < 2) {
            // K: defaults (Wh -> HM, epi 4, sc=1)
        } else if (y < 4) {
            Wuse = Wl; HMuse = HM2; epiu = 5;
            bn = (y - 2) * 128;
        } else {
            if (blockIdx.x >= MQ / 128) return;    // Q covers 33 x-blocks
            Wuse = Wq2; HMuse = HMq; epiu = 4;
            bn = (y - 4) * 128;
            Nloc = DD; asll = NU; astl = TT; asol = CS; SEQl = NU;
            scl = 0.125f;
        }
    }

    auto load_chunk = [&](int p, int c) {
        const int kc = c << 6;
        uint32_t bufb = sb + 1024 + p * SS;
        #pragma unroll
        for (int i = tid; i < 1024; i += 256) {
            int r = i >> 3, seg = i & 7;
            int row = bm + r;
            size_t ar = (size_t)(row / asll) * astl + asol + (row % asll);
            uint32_t off = (r << 7) + (seg << 4);
            uint32_t sw = off ^ ((off >> 3) & 0x70);
            CP_ASYNC16(bufb + sw, Ah + ar * K + kc + seg * 8);
        }
        #pragma unroll
        for (int i = tid; i < 1024; i += 256) {
            int r = i >> 3, seg = i & 7;
            uint32_t off = (r << 7) + (seg << 4);
            uint32_t sw = off ^ ((off >> 3) & 0x70);
            CP_ASYNC16(bufb + 16384 + sw, Wuse + (size_t)(bn + r) * K + kc + seg * 8);
        }
        CP_COMMIT();
    };

    const int warp_m = wid >> 1;
    const int warp_n = wid & 1;

    float acc[2][8][4];
    uint32_t acch[2][8][2];
    #pragma unroll
    for (int mf = 0; mf < 2; mf++)
        #pragma unroll
        for (int nf = 0; nf < 8; nf++) {
            if (FACC) { acch[mf][nf][0] = 0u; acch[mf][nf][1] = 0u; }
            else {
                #pragma unroll
                for (int j = 0; j < 4; j++) acc[mf][nf][j] = 0.f;
            }
        }

    load_chunk(0, 0);
    if (nchunks > 1) load_chunk(1, 1);

    const int a_row = warp_m * 32 + (lane & 15);
    const uint32_t a_koff = (lane >> 4) << 4;
    const int b_row = warp_n * 64 + ((lane >> 4) << 3) + (lane & 7);
    const uint32_t b_koff = ((lane >> 3) & 1) << 4;

    for (int c = 0; c < nchunks; c++) {
        if (c + 1 < nchunks) CP_WAIT(1);
        else CP_WAIT(0);
        __syncthreads();

        const uint32_t bA = sb + 1024 + (uint32_t)(c % 3) * SS;
        const uint32_t bW = bA + 16384;

        #pragma unroll
        for (int ks = 0; ks < 4; ks++) {
            const uint32_t kb = ks * 32;
            uint32_t ah[2][4];
            #pragma unroll
            for (int mf = 0; mf < 2; mf++) {
                uint32_t off = ((uint32_t)(a_row + mf * 16) << 7) + kb + a_koff;
                off ^= (off >> 3) & 0x70;
                ldsm4(ah[mf][0], ah[mf][1], ah[mf][2], ah[mf][3], bA + off);
            }
            #pragma unroll
            for (int nf2 = 0; nf2 < 4; nf2++) {
                uint32_t off = ((uint32_t)(b_row + nf2 * 16) << 7) + kb + b_koff;
                off ^= (off >> 3) & 0x70;
                uint32_t w0, w1, w2, w3;
                ldsm4(w0, w1, w2, w3, bW + off);
                uint32_t bb0[2] = {w0, w1}, bb1[2] = {w2, w3};
                if (FACC) {
                    mma_f16h(acch[0][2*nf2],   ah[0], bb0);
                    mma_f16h(acch[0][2*nf2+1], ah[0], bb1);
                    mma_f16h(acch[1][2*nf2],   ah[1], bb0);
                    mma_f16h(acch[1][2*nf2+1], ah[1], bb1);
                } else {
                    mma_f16(acc[0][2*nf2],   ah[0], bb0);
                    mma_f16(acc[0][2*nf2+1], ah[0], bb1);
                    mma_f16(acc[1][2*nf2],   ah[1], bb0);
                    mma_f16(acc[1][2*nf2+1], ah[1], bb1);
                }
            }
        }
        if (c + 2 < nchunks) load_chunk((c + 2) % 3, c + 2);
    }

    if (FACC) {
        #pragma unroll
        for (int mf = 0; mf < 2; mf++)
            #pragma unroll
            for (int nf = 0; nf < 8; nf++) {
                float2 lo = __half22float2(u2h(acch[mf][nf][0]));
                float2 hi = __half22float2(u2h(acch[mf][nf][1]));
                acc[mf][nf][0] = lo.x; acc[mf][nf][1] = lo.y;
                acc[mf][nf][2] = hi.x; acc[mf][nf][3] = hi.y;
            }
    }

    // ---- epilogue ----
    const int rq = lane >> 2, cq = (lane & 3) << 1;
    if (epiu >= 4) {
        const int headw = (bn + warp_n * 64) >> 6;
        const int heads = Nloc >> 6;
        #pragma unroll
        for (int mf = 0; mf < 2; mf++) {
            #pragma unroll
            for (int h2 = 0; h2 < 2; h2++) {
                const int rowg = bm + warp_m * 32 + mf * 16 + rq + h2 * 8;
                float s = 1.0f;
                if (epiu == 4) {
                    float ss = 0.f;
                    #pragma unroll
                    for (int nf = 0; nf < 8; nf++) {
                        float x0 = acc[mf][nf][2*h2], x1 = acc[mf][nf][2*h2+1];
                        ss += x0 * x0 + x1 * x1;
                    }
                    ss += __shfl_xor_sync(0xffffffffu, ss, 1);
                    ss += __shfl_xor_sync(0xffffffffu, ss, 2);
                    s = scl / fmaxf(sqrtf(ss), 1e-12f);
                }
                int b = rowg / SEQl, t = rowg - b * SEQl;
                __half* dst = HMuse + (((size_t)(b * heads + headw)) * SEQl + t) * 64;
                #pragma unroll
                for (int nf = 0; nf < 8; nf++) {
                    float x0 = acc[mf][nf][2*h2] * s, x1 = acc[mf][nf][2*h2+1] * s;
                    *(__half2*)(dst + nf * 8 + cq) = __floats2half2_rn(x0, x1);
                }
            }
        }
    } else {
        #pragma unroll
        for (int mf = 0; mf < 2; mf++) {
            #pragma unroll
            for (int h2 = 0; h2 < 2; h2++) {
                const int rowg = bm + warp_m * 32 + mf * 16 + rq + h2 * 8;
                #pragma unroll
                for (int nf = 0; nf < 8; nf++) {
                    float x0 = acc[mf][nf][2*h2], x1 = acc[mf][nf][2*h2+1];
                    const int colg = bn + warp_n * 64 + nf * 8 + cq;
                    if (epiu == 1) {
                        size_t rr = (size_t)(rowg / rsl) * rst + rso + (rowg % rsl);
                        const float* rp = R + rr * Nloc + colg;
                        float2 o;
                        o.x = rp[0] + 15.0f * tanhfast(x0 * (1.0f/15.0f));
                        o.y = rp[1] + 15.0f * tanhfast(x1 * (1.0f/15.0f));
                        *(float2*)(C + (size_t)rowg * Nloc + colg) = o;
                    } else if (epiu == 2) {
                        float a = fmaxf(x0, 0.f); a *= a;
                        float b = fmaxf(x1, 0.f); b *= b;
                        *(__half2*)(Ch + (size_t)rowg * Nloc + colg) = __floats2half2_rn(a, b);
                    } else {
                        const float* rp = R + (size_t)rowg * Nloc + colg;
                        size_t cr = (size_t)(rowg / rsl) * rst + rso + (rowg % rsl);
                        *(float2*)(C + cr * Nloc + colg) =
                            make_float2(rp[0] + x0, rp[1] + x1);
                    }
                }
            }
        }
    }
}

// ============================================================
// Flash attention, 2 heads/CTA, 128 thr / 4 warps, 32 q-rows/warp.
// (round-11 verified configuration, byte-identical numerics)
// smem: Q 2x8KB @0; 2 KV stages of 16KB @16384. Total 49152.
// ============================================================
__global__ __launch_bounds__(128, 2) void attn_mma(
    const __half* __restrict__ qbf,
    const __half* __restrict__ kbf,
    const __half* __restrict__ vbf,
    __half* __restrict__ o)
{
    extern __shared__ char sm[];
    const uint32_t sb = smem_u32(sm);
    const int tid = threadIdx.x;
    const int w = tid >> 5, l = tid & 31;
    const int wp = w >> 1;
    const int wh = w & 1;
    const int qt = (int)gridDim.x - 1 - (int)blockIdx.x;
    const int y = blockIdx.y;
    const int b = y >> 3, hp = y & 7;
    const int head = hp * 2 + wp;
    const int kvh = hp >> 1;
    const int q0 = qt * 64;

    const __half* kg = kbf + ((size_t)(b * KVH + kvh) * TT) * 64;
    const __half* vg = vbf + ((size_t)(b * KVH + kvh) * TT) * 64;

    for (int i = tid; i < 1024; i += 128) {
        int hpi = i >> 9;
        int rem = i & 511;
        int r = rem >> 3, seg = rem & 7;
        const __half* src = qbf + (((size_t)(b * 16 + hp * 2 + hpi)) * NU + q0 + r) * 64 + seg * 8;
        uint32_t off = (r << 7) + (seg << 4);
        uint32_t swo = off ^ ((off >> 3) & 0x70);
        CP_ASYNC16(sb + hpi * 8192 + swo, src);
    }
    const int n_kt = (CS >> 6) + qt + 1;
    auto load_kv = [&](int p, int c) {
        uint32_t base = sb + 16384 + p * 16384;
        const __half* ks = kg + (size_t)(c << 6) * 64;
        const __half* vs = vg + (size_t)(c << 6) * 64;
        for (int i = tid; i < 1024; i += 128) {
            int half = i >> 9;
            int rem = i & 511;
            int r = rem >> 3, seg = rem & 7;
            uint32_t off = (r << 7) + (seg << 4);
            uint32_t swo = off ^ ((off >> 3) & 0x70);
            const __half* src = (half ? vs : ks) + r * 64 + seg * 8;
            CP_ASYNC16(base + half * 8192 + swo, src);
        }
        CP_COMMIT();
    };
    load_kv(0, 0);

    float o_acc[2][8][4];
    #pragma unroll
    for (int mf = 0; mf < 2; mf++)
        #pragma unroll
        for (int j = 0; j < 8; j++)
            #pragma unroll
            for (int i = 0; i < 4; i++) o_acc[mf][j][i] = 0.f;
    float rsum[2][2] = {{0.f, 0.f}, {0.f, 0.f}};

    const int lrow = l & 15;
    const int lhi = l >> 4;
    const int cq = (l & 3) << 1;
    const int qpos0 = CS + q0 + wh * 32 + (l >> 2);
    const uint32_t qbase = sb + wp * 8192;

    const __half2 C6 = __float2half2_rn(0.16666667f);
    const __half2 C5 = __float2half2_rn(0.5f);
    const __half2 C1 = __float2half2_rn(1.0f);

    for (int c = 0; c < n_kt; c++) {
        const int p = c & 1;
        if (c + 1 < n_kt) { load_kv(1 - p, c + 1); CP_WAIT(1); }
        else              { CP_WAIT(0); }
        __syncthreads();
        const uint32_t kbase = sb + 16384 + p * 16384;
        const uint32_t vbase = kbase + 8192;

        // ---- S = Q K^T (fp16 accumulators, 2 A-frags per warp) ----
        uint32_t sh[2][8][2];
        #pragma unroll
        for (int mf = 0; mf < 2; mf++)
            #pragma unroll
            for (int j = 0; j < 8; j++) { sh[mf][j][0] = 0u; sh[mf][j][1] = 0u; }
        #pragma unroll
        for (int ks = 0; ks < 4; ks++) {
            uint32_t a[2][4];
            #pragma unroll
            for (int mf = 0; mf < 2; mf++) {
                uint32_t off = ((uint32_t)(wh * 32 + mf * 16 + lrow) << 7)
                             + ks * 32 + (lhi << 4);
                off ^= (off >> 3) & 0x70;
                ldsm4(a[mf][0], a[mf][1], a[mf][2], a[mf][3], qbase + off);
            }
            #pragma unroll
            for (int j = 0; j < 8; j += 2) {
                uint32_t off = ((uint32_t)((j + lhi) * 8 + (l & 7)) << 7)
                             + ks * 32 + (((l >> 3) & 1) << 4);
                off ^= (off >> 3) & 0x70;
                uint32_t b0, b1, b2, b3;
                ldsm4(b0, b1, b2, b3, kbase + off);
                uint32_t bb0[2] = {b0, b1}, bb1[2] = {b2, b3};
                mma_f16h(sh[0][j],     a[0], bb0);
                mma_f16h(sh[0][j + 1], a[0], bb1);
                mma_f16h(sh[1][j],     a[1], bb0);
                mma_f16h(sh[1][j + 1], a[1], bb1);
            }
        }

        // ---- P = exp(S) cubic poly on half2 ----
        #pragma unroll
        for (int mf = 0; mf < 2; mf++)
            #pragma unroll
            for (int j = 0; j < 8; j++) {
                #pragma unroll
                for (int r = 0; r < 2; r++) {
                    __half2 yv = u2h(sh[mf][j][r]);
                    __half2 t = __hfma2(yv, C6, C5);
                    t = __hfma2(yv, t, C1);
                    sh[mf][j][r] = h2u(__hfma2(yv, t, C1));
                }
            }

        // ---- causal zero-mask on diagonal tile ----
        if (c == n_kt - 1) {
            const int k0c = c * 64;
            #pragma unroll
            for (int mf = 0; mf < 2; mf++) {
                const int qp = qpos0 + mf * 16;
                #pragma unroll
                for (int j = 0; j < 8; j++) {
                    int col0 = k0c + j * 8 + cq;
                    float2 f0 = __half22float2(u2h(sh[mf][j][0]));
                    if (col0     > qp) f0.x = 0.f;
                    if (col0 + 1 > qp) f0.y = 0.f;
                    sh[mf][j][0] = packh2(f0.x, f0.y);
                    float2 f1 = __half22float2(u2h(sh[mf][j][1]));
                    if (col0     > qp + 8) f1.x = 0.f;
                    if (col0 + 1 > qp + 8) f1.y = 0.f;
                    sh[mf][j][1] = packh2(f1.x, f1.y);
                }
            }
        }

        // ---- row sums ----
        #pragma unroll
        for (int mf = 0; mf < 2; mf++) {
            __half2 t0 = u2h(sh[mf][0][0]), t1 = u2h(sh[mf][0][1]);
            #pragma unroll
            for (int j = 1; j < 8; j++) {
                t0 = __hadd2(t0, u2h(sh[mf][j][0]));
                t1 = __hadd2(t1, u2h(sh[mf][j][1]));
            }
            float2 f0 = __half22float2(t0);
            float2 f1 = __half22float2(t1);
            rsum[mf][0] += f0.x + f0.y;
            rsum[mf][1] += f1.x + f1.y;
        }

        // ---- O += P V (f32 acc; each V ldsm feeds both mf) ----
        #pragma unroll
        for (int ks = 0; ks < 4; ks++) {
            uint32_t a0[4] = {sh[0][2*ks][0], sh[0][2*ks][1], sh[0][2*ks+1][0], sh[0][2*ks+1][1]};
            uint32_t a1[4] = {sh[1][2*ks][0], sh[1][2*ks][1], sh[1][2*ks+1][0], sh[1][2*ks+1][1]};
            #pragma unroll
            for (int j = 0; j < 8; j += 2) {
                uint32_t off = ((uint32_t)(ks * 16 + lrow) << 7) + ((j + lhi) << 4);
                off ^= (off >> 3) & 0x70;
                uint32_t b0, b1, b2, b3;
                ldsm4t(b0, b1, b2, b3, vbase + off);
                uint32_t bb0[2] = {b0, b1}, bb1[2] = {b2, b3};
                mma_f16(o_acc[0][j],     a0, bb0);
                mma_f16(o_acc[0][j + 1], a0, bb1);
                mma_f16(o_acc[1][j],     a1, bb0);
                mma_f16(o_acc[1][j + 1], a1, bb1);
            }
        }
        __syncthreads();
    }

    #pragma unroll
    for (int mf = 0; mf < 2; mf++) {
        float r0 = rsum[mf][0], r1 = rsum[mf][1];
        r0 += __shfl_xor_sync(0xffffffffu, r0, 1);
        r0 += __shfl_xor_sync(0xffffffffu, r0, 2);
        r1 += __shfl_xor_sync(0xffffffffu, r1, 1);
        r1 += __shfl_xor_sync(0xffffffffu, r1, 2);
        const float inv0 = 1.0f / r0, inv1 = 1.0f / r1;

        const size_t gr0 = (size_t)(b * NU + q0 + wh * 32 + mf * 16 + (l >> 2));
        const size_t gr1 = gr0 + 8;
        const int colb = head * 64 + cq;
        #pragma unroll
        for (int j = 0; j < 8; j++) {
            const int col = colb + j * 8;
            *(__half2*)(o + gr0 * DD + col) =
                __floats2half2_rn(o_acc[mf][j][0] * inv0, o_acc[mf][j][1] * inv0);
            *(__half2*)(o + gr1 * DD + col) =
                __floats2half2_rn(o_acc[mf][j][2] * inv1, o_acc[mf][j][3] * inv1);
        }
    }
}

// ============================================================
extern "C" void kernel_launch(void* const* d_in, const int* in_sizes, int n_in,
                              void* d_out, int out_size)
{
    const float* x     = (const float*)d_in[0];
    const float* Wq    = (const float*)d_in[1];
    const float* Wk    = (const float*)d_in[2];
    const float* Wv    = (const float*)d_in[3];
    const float* Wo    = (const float*)d_in[4];
    const float* Wfc   = (const float*)d_in[5];
    const float* Wproj = (const float*)d_in[6];
    float* out = (float*)d_out;

    __half *xnf, *qbf, *kbf, *vbf, *af, *x2f, *hf;
    __half *wq, *wk, *wv, *wo, *wf, *wp;
    float *xnew;
    cudaGetSymbolAddress((void**)&xnf, g_xnf);
    cudaGetSymbolAddress((void**)&qbf, g_qbf);
    cudaGetSymbolAddress((void**)&kbf, g_kbf);
    cudaGetSymbolAddress((void**)&vbf, g_vbf);
    cudaGetSymbolAddress((void**)&af,  g_af);
    cudaGetSymbolAddress((void**)&xnew, g_xnew);
    cudaGetSymbolAddress((void**)&x2f, g_x2f);
    cudaGetSymbolAddress((void**)&hf,  g_hf);
    cudaGetSymbolAddress((void**)&wq,  g_wq);
    cudaGetSymbolAddress((void**)&wk,  g_wk);
    cudaGetSymbolAddress((void**)&wv,  g_wv);
    cudaGetSymbolAddress((void**)&wo,  g_wo);
    cudaGetSymbolAddress((void**)&wf,  g_wf);
    cudaGetSymbolAddress((void**)&wp,  g_wp);

    const int SMG = 1024 + 3 * 32768;   // 99328
    const int SMA = 49152;              // Q 16K + 2x16K
    cudaFuncSetAttribute(gemm_tc<true>,  cudaFuncAttributeMaxDynamicSharedMemorySize, SMG);
    cudaFuncSetAttribute(gemm_tc<false>, cudaFuncAttributeMaxDynamicSharedMemorySize, SMG);
    cudaFuncSetAttribute(attn_mma, cudaFuncAttributeMaxDynamicSharedMemorySize, SMA);

    // 1. fused prologue
    prep_k<<<17792, 256>>>(x, Wq, Wk, Wv, Wo, Wfc, Wproj,
                           out, xnf, wq, wk, wv, wo, wf, wp);

    // 2. merged QKV projection: y<2 K, y<4 V (both M=MX), y>=4 Q (M=MQ, x<33)
    gemm_tc<true><<<dim3(MX / 128, 12), 256, SMG>>>(xnf, wk, wv,
        nullptr, nullptr, kbf, vbf, nullptr, wq, qbf,
        KVD, DD, MX, MX, 0, 0, 0, 0, TT, 1.0f, 4, 2);

    // 3. flash attention (2 heads/CTA, 32 rows/warp — round-11 config)
    attn_mma<<<dim3(NU / 64, BB * 8), 128, SMA>>>(qbf, kbf, vbf, af);

    // 4. x_new = x_upd + softcap(attn @ Wo^T), fp16 acc
    gemm_tc<true><<<dim3(MQ / 128, DD / 128), 256, SMG>>>(af, wo, nullptr,
        xnew, nullptr, nullptr, nullptr, x, nullptr, nullptr,
        DD, DD, MQ, MQ, 0, NU, TT, CS, 0, 0.f, 1, 0);

    // 5. FFN (f32 acc)
    rms_k<<<MQ, 256>>>(xnew, x2f);
    gemm_tc<false><<<dim3(MQ / 128, DFF / 128), 256, SMG>>>(x2f, wf, nullptr,
        nullptr, hf, nullptr, nullptr, nullptr, nullptr, nullptr,
        DFF, DD, MQ, MQ, 0, 0, 0, 0, 0, 0.f, 2, 0);
    gemm_tc<false><<<dim3(MQ / 128, DD / 128), 256, SMG>>>(hf, wp, nullptr,
        out, nullptr, nullptr, nullptr, xnew, nullptr, nullptr,
        DD, DFF, MQ, MQ, 0, NU, TT, CS, 0, 0.f, 3, 0);
}